// round 11
// baseline (speedup 1.0000x reference)
#include <cuda_runtime.h>
#include <cstdint>

#define N_NODES 100000
#define N_EDGES 1000000
#define D 64
#define LATENT 32
#define OUT_DIM 64
#define SC_BLOCKS 3125             // 3125 * 5120 = 16M items exactly
#define NB_NODE 1563               // ceil(100k / 64)
#define XS2_STRIDE 66              // float2 units; 528B rows -> 16B aligned

// Scratch (BSS-zeroed at load; B re-zeros consumed tiles each call)
__device__ float g_sums[(size_t)N_NODES * D];       // 25.6 MB edge sums
__device__ float g_cnt[N_NODES];
__device__ float g_hpre[(size_t)N_NODES * LATENT];  // node_attr @ W1[0:64]
__device__ float g_G[64 * LATENT];                  // global @ W1[128:192] + b1

// ---------------------------------------------------------------------------
// f32x2 packed helpers (Blackwell FFMA2 — only reachable via PTX)
// ---------------------------------------------------------------------------
__device__ __forceinline__ uint64_t pack2(float a, float b) {
    uint64_t r; asm("mov.b64 %0, {%1, %2};" : "=l"(r) : "f"(a), "f"(b)); return r;
}
__device__ __forceinline__ void unpack2(uint64_t v, float& a, float& b) {
    asm("mov.b64 {%0, %1}, %2;" : "=f"(a), "=f"(b) : "l"(v));
}
__device__ __forceinline__ void ffma2(uint64_t& acc, uint64_t x, uint64_t w) {
    asm("fma.rn.f32x2 %0, %1, %2, %0;" : "+l"(acc) : "l"(x), "l"(w));
}
__device__ __forceinline__ void red_add_v4(float* dst, float4 v) {
    asm volatile("red.global.add.v4.f32 [%0], {%1, %2, %3, %4};"
                 :: "l"(dst), "f"(v.x), "f"(v.y), "f"(v.z), "f"(v.w) : "memory");
}

// ---------------------------------------------------------------------------
// Kernel A: [batched edge scatter | node-proj | G]
// ---------------------------------------------------------------------------
__global__ __launch_bounds__(256)
void scatter_kernel(const float* __restrict__ edge_attr,
                    const int* __restrict__ recv,
                    const float* __restrict__ node_attr,
                    const float* __restrict__ global_attr,
                    const float* __restrict__ W1,
                    const float* __restrict__ b1) {
    __shared__ float sW[2048];   // 8 KB weight tile (node-proj / G branches)
    __shared__ float sb[LATENT];
    const int tid = threadIdx.x;

    if (blockIdx.x < SC_BLOCKS) {
        // ===== edge scatter: 5120 items/block, 20/thread, no predicates =====
        const int cc = tid & 15;                      // loop-invariant chunk id
        const long long base = (long long)blockIdx.x * 5120 + tid;
        #pragma unroll
        for (int g = 0; g < 5; g++) {
            float4 v[4]; int rr[4];
            #pragma unroll
            for (int u = 0; u < 4; u++) {
                int e = (int)((base + (long long)(g * 4 + u) * 256) >> 4);
                v[u]  = __ldg(&reinterpret_cast<const float4*>(edge_attr)
                                  [(size_t)e * 16 + cc]);
                rr[u] = __ldg(&recv[e]);
            }
            #pragma unroll
            for (int u = 0; u < 4; u++) {
                red_add_v4(g_sums + (size_t)rr[u] * D + cc * 4, v[u]);
                if (cc == 0) atomicAdd(&g_cnt[rr[u]], 1.0f);
            }
        }
        return;
    }

    if (blockIdx.x < SC_BLOCKS + NB_NODE) {
        // ===== node projection: hpre[n][j] = node[n][0:64] . W1[0:64][j] =====
        const int tile = (blockIdx.x - SC_BLOCKS) * 64;
        const int lane = tid & 31, p = tid >> 5;
        for (int i = tid; i < D * LATENT; i += 256) sW[i] = W1[i];
        __syncthreads();

        const int n0 = tile + p * 8;
        float acc[8] = {};
        #pragma unroll 4
        for (int k4 = 0; k4 < 16; k4++) {
            float w0 = sW[(4 * k4 + 0) * LATENT + lane];
            float w1 = sW[(4 * k4 + 1) * LATENT + lane];
            float w2 = sW[(4 * k4 + 2) * LATENT + lane];
            float w3 = sW[(4 * k4 + 3) * LATENT + lane];
            #pragma unroll
            for (int i = 0; i < 8; i++) {
                int n = n0 + i;
                if (n < N_NODES) {
                    float4 x = __ldg(&reinterpret_cast<const float4*>(node_attr)
                                         [(size_t)n * 16 + k4]);
                    acc[i] = fmaf(x.x, w0, acc[i]);
                    acc[i] = fmaf(x.y, w1, acc[i]);
                    acc[i] = fmaf(x.z, w2, acc[i]);
                    acc[i] = fmaf(x.w, w3, acc[i]);
                }
            }
        }
        #pragma unroll
        for (int i = 0; i < 8; i++) {
            int n = n0 + i;
            if (n < N_NODES) g_hpre[(size_t)n * LATENT + lane] = acc[i];
        }
        return;
    }

    // ===== G[b][j] = b1[j] + global[b] . W1[128:192][j] =====
    {
        const int lane = tid & 31;
        for (int i = tid; i < D * LATENT; i += 256)
            sW[i] = W1[2 * D * LATENT + i];
        if (tid < LATENT) sb[tid] = b1[tid];
        __syncthreads();

        const int r0 = (tid >> 5) * 8;
        float acc[8];
        #pragma unroll
        for (int i = 0; i < 8; i++) acc[i] = sb[lane];
        #pragma unroll 4
        for (int k4 = 0; k4 < 16; k4++) {
            float w0 = sW[(4 * k4 + 0) * LATENT + lane];
            float w1 = sW[(4 * k4 + 1) * LATENT + lane];
            float w2 = sW[(4 * k4 + 2) * LATENT + lane];
            float w3 = sW[(4 * k4 + 3) * LATENT + lane];
            #pragma unroll
            for (int i = 0; i < 8; i++) {
                float4 x = __ldg(&reinterpret_cast<const float4*>(global_attr)
                                     [(size_t)(r0 + i) * 16 + k4]);
                acc[i] = fmaf(x.x, w0, acc[i]);
                acc[i] = fmaf(x.y, w1, acc[i]);
                acc[i] = fmaf(x.z, w2, acc[i]);
                acc[i] = fmaf(x.w, w3, acc[i]);
            }
        }
        #pragma unroll
        for (int i = 0; i < 8; i++) g_G[(r0 + i) * LATENT + lane] = acc[i];
    }
}

// ---------------------------------------------------------------------------
// Kernel B: mean staging + edge-half layer1 (FFMA2, LDS.128) + relu + layer2.
// Block = 64-node tile; warp owns 8 nodes. Stride-66 (16B-aligned rows).
// ---------------------------------------------------------------------------
__global__ __launch_bounds__(256)
void mlp_kernel(const float* __restrict__ W1,
                const float* __restrict__ W2,
                const float* __restrict__ b2,
                const int* __restrict__ ng,
                float* __restrict__ out) {
    __shared__ __align__(16) float2 sW1b[1024];            // 8 KB, W1 rows 64..127
    __shared__ float sW2[LATENT * OUT_DIM];                // 8 KB
    __shared__ float sb2[OUT_DIM];
    __shared__ __align__(16) float2 xs2[32 * XS2_STRIDE];  // 16.9 KB (reused for h)

    const int tid = threadIdx.x;
    const int tile = blockIdx.x * 64;
    const int lane = tid & 31, p = tid >> 5;
    const int nbase = tile + p * 8;

    for (int idx = tid; idx < 1024; idx += 256) {
        int k2 = idx >> 5, j = idx & 31;
        sW1b[idx] = make_float2(W1[(D + 2 * k2) * LATENT + j],
                                (float)W1[(D + 2 * k2 + 1) * LATENT + j]);
    }
    for (int i = tid; i < LATENT * OUT_DIM; i += 256) sW2[i] = W2[i];
    if (tid < OUT_DIM) sb2[tid] = b2[tid];

    // init accumulators: lo = hpre + G, hi = 0
    uint64_t a2[8];
    #pragma unroll
    for (int i = 0; i < 8; i++) {
        int n = nbase + i;
        float init = 0.f;
        if (n < N_NODES) {
            int g = __ldg(&ng[n]);
            init = g_hpre[(size_t)n * LATENT + lane] + g_G[g * LATENT + lane];
        }
        a2[i] = pack2(init, 0.f);
    }

    // stage mean aggregated edges, interleaved-k float2
    const int kq = tid & 15, srow = tid >> 4;
    #pragma unroll
    for (int it = 0; it < 4; it++) {
        int nn = it * 16 + srow, n = tile + nn;
        float4 v = make_float4(0.f, 0.f, 0.f, 0.f);
        if (n < N_NODES) {
            v = reinterpret_cast<const float4*>(g_sums)[(size_t)n * 16 + kq];
            float inv = 1.0f / fmaxf(g_cnt[n], 1.0f);
            v.x *= inv; v.y *= inv; v.z *= inv; v.w *= inv;
        }
        xs2[(2 * kq + 0) * XS2_STRIDE + nn] = make_float2(v.x, v.y);
        xs2[(2 * kq + 1) * XS2_STRIDE + nn] = make_float2(v.z, v.w);
    }
    __syncthreads();

    // re-zero this tile's scratch — FULL rows: 64 nodes x 16 float4
    {
        float4 z = make_float4(0.f, 0.f, 0.f, 0.f);
        #pragma unroll
        for (int s = 0; s < 4; s++) {
            int item = tid + 256 * s;             // 0..1023
            int n = tile + (item >> 4);
            if (n < N_NODES)
                reinterpret_cast<float4*>(g_sums)[(size_t)n * 16 + (item & 15)] = z;
        }
        if (tid < 64 && tile + tid < N_NODES) g_cnt[tile + tid] = 0.f;
    }

    // edge half of layer 1: FFMA2 over k-pairs, x via LDS.128
    #pragma unroll 4
    for (int k2 = 0; k2 < 32; k2++) {
        uint64_t w2 = *reinterpret_cast<const uint64_t*>(&sW1b[k2 * 32 + lane]);
        const ulonglong2* xr =
            reinterpret_cast<const ulonglong2*>(&xs2[k2 * XS2_STRIDE + p * 8]);
        ulonglong2 xa = xr[0], xb = xr[1], xc = xr[2], xd = xr[3];
        ffma2(a2[0], xa.x, w2); ffma2(a2[1], xa.y, w2);
        ffma2(a2[2], xb.x, w2); ffma2(a2[3], xb.y, w2);
        ffma2(a2[4], xc.x, w2); ffma2(a2[5], xc.y, w2);
        ffma2(a2[6], xd.x, w2); ffma2(a2[7], xd.y, w2);
    }
    __syncthreads();   // xs2 reads done; reuse as h buffer

    // relu, park h j-major (two STS.128)
    float* hs2 = reinterpret_cast<float*>(xs2);
    float h[8];
    #pragma unroll
    for (int i = 0; i < 8; i++) {
        float lo, hi; unpack2(a2[i], lo, hi);
        h[i] = fmaxf(lo + hi, 0.f);
    }
    {
        ulonglong2 t0, t1;
        t0.x = pack2(h[0], h[1]); t0.y = pack2(h[2], h[3]);
        t1.x = pack2(h[4], h[5]); t1.y = pack2(h[6], h[7]);
        ulonglong2* dst = reinterpret_cast<ulonglong2*>(
            &hs2[lane * (2 * XS2_STRIDE) + p * 8]);
        dst[0] = t0; dst[1] = t1;
    }
    __syncthreads();

    // layer 2: h via LDS.128
    uint64_t o2[4][2];
    #pragma unroll
    for (int q = 0; q < 4; q++) {
        o2[q][0] = pack2(sb2[lane], sb2[lane]);
        o2[q][1] = pack2(sb2[lane + 32], sb2[lane + 32]);
    }
    #pragma unroll 4
    for (int j = 0; j < LATENT; j++) {
        float wa = sW2[j * OUT_DIM + lane];
        float wb = sW2[j * OUT_DIM + lane + 32];
        uint64_t w0 = pack2(wa, wa);
        uint64_t w1 = pack2(wb, wb);
        const ulonglong2* hr = reinterpret_cast<const ulonglong2*>(
            &hs2[j * (2 * XS2_STRIDE) + p * 8]);
        ulonglong2 ha = hr[0], hb = hr[1];
        ffma2(o2[0][0], ha.x, w0); ffma2(o2[0][1], ha.x, w1);
        ffma2(o2[1][0], ha.y, w0); ffma2(o2[1][1], ha.y, w1);
        ffma2(o2[2][0], hb.x, w0); ffma2(o2[2][1], hb.x, w1);
        ffma2(o2[3][0], hb.y, w0); ffma2(o2[3][1], hb.y, w1);
    }

    #pragma unroll
    for (int q = 0; q < 4; q++) {
        int n0 = nbase + 2 * q;
        float a0, c0, a1, c1;
        unpack2(o2[q][0], a0, c0);
        unpack2(o2[q][1], a1, c1);
        if (n0 < N_NODES) {
            out[(size_t)n0 * OUT_DIM + lane]      = a0;
            out[(size_t)n0 * OUT_DIM + lane + 32] = a1;
        }
        if (n0 + 1 < N_NODES) {
            out[(size_t)(n0 + 1) * OUT_DIM + lane]      = c0;
            out[(size_t)(n0 + 1) * OUT_DIM + lane + 32] = c1;
        }
    }
}

// ---------------------------------------------------------------------------
// Kernel C: nop (makes L=3 so ncu -s 5 -c 1 captures the scatter kernel)
// ---------------------------------------------------------------------------
__global__ void nop_kernel() {}

// ---------------------------------------------------------------------------
extern "C" void kernel_launch(void* const* d_in, const int* in_sizes, int n_in,
                              void* d_out, int out_size) {
    const float* node_attr   = (const float*)d_in[0];
    const float* edge_attr   = (const float*)d_in[1];
    const float* global_attr = (const float*)d_in[2];
    const float* W1          = (const float*)d_in[3];
    const float* b1          = (const float*)d_in[4];
    const float* W2          = (const float*)d_in[5];
    const float* b2          = (const float*)d_in[6];
    const int*   recv        = (const int*)d_in[7];
    const int*   ng          = (const int*)d_in[8];
    float* out = (float*)d_out;

    // A) batched edge scatter + node projection + G
    scatter_kernel<<<SC_BLOCKS + NB_NODE + 1, 256>>>(edge_attr, recv, node_attr,
                                                     global_attr, W1, b1);

    // B) mean + edge-half layer1 + relu + layer2 (+ scratch re-zero)
    mlp_kernel<<<(N_NODES + 63) / 64, 256>>>(W1, W2, b2, ng, out);

    // C) nop — shifts ncu capture onto scatter_kernel
    nop_kernel<<<1, 32>>>();
}

// round 12
// speedup vs baseline: 1.0137x; 1.0137x over previous
#include <cuda_runtime.h>
#include <cstdint>

#define N_NODES 100000
#define N_EDGES 1000000
#define D 64
#define LATENT 32
#define OUT_DIM 64
#define SC_BLOCKS 3125             // 3125 * 5120 = 16M items exactly
#define NB_NODE 1563               // ceil(100k / 64)
#define XS2_STRIDE 66              // float2 units; 528B rows -> 16B aligned

// Scratch (BSS-zeroed at load; B re-zeros consumed tiles each call)
__device__ float g_sums[(size_t)N_NODES * D];       // 25.6 MB edge sums
__device__ float g_cnt[N_NODES];
__device__ float g_hpre[(size_t)N_NODES * LATENT];  // node_attr @ W1[0:64]
__device__ float g_G[64 * LATENT];                  // global @ W1[128:192] + b1

// ---------------------------------------------------------------------------
// f32x2 packed helpers (Blackwell FFMA2 — only reachable via PTX)
// ---------------------------------------------------------------------------
__device__ __forceinline__ uint64_t pack2(float a, float b) {
    uint64_t r; asm("mov.b64 %0, {%1, %2};" : "=l"(r) : "f"(a), "f"(b)); return r;
}
__device__ __forceinline__ void unpack2(uint64_t v, float& a, float& b) {
    asm("mov.b64 {%0, %1}, %2;" : "=f"(a), "=f"(b) : "l"(v));
}
__device__ __forceinline__ void ffma2(uint64_t& acc, uint64_t x, uint64_t w) {
    asm("fma.rn.f32x2 %0, %1, %2, %0;" : "+l"(acc) : "l"(x), "l"(w));
}
__device__ __forceinline__ void red_add_v4(float* dst, float4 v) {
    asm volatile("red.global.add.v4.f32 [%0], {%1, %2, %3, %4};"
                 :: "l"(dst), "f"(v.x), "f"(v.y), "f"(v.z), "f"(v.w) : "memory");
}

// ---------------------------------------------------------------------------
// Kernel A: [batched edge scatter | node-proj | G]
// ---------------------------------------------------------------------------
__global__ __launch_bounds__(256)
void scatter_kernel(const float* __restrict__ edge_attr,
                    const int* __restrict__ recv,
                    const float* __restrict__ node_attr,
                    const float* __restrict__ global_attr,
                    const float* __restrict__ W1,
                    const float* __restrict__ b1) {
    __shared__ float sW[2048];   // 8 KB weight tile (node-proj / G branches)
    __shared__ float sb[LATENT];
    const int tid = threadIdx.x;

    if (blockIdx.x < SC_BLOCKS) {
        // ===== edge scatter: 5120 items/block, 20/thread, no predicates =====
        const int cc = tid & 15;                      // loop-invariant chunk id
        const long long base = (long long)blockIdx.x * 5120 + tid;
        #pragma unroll
        for (int g = 0; g < 5; g++) {
            float4 v[4]; int rr[4];
            #pragma unroll
            for (int u = 0; u < 4; u++) {
                int e = (int)((base + (long long)(g * 4 + u) * 256) >> 4);
                v[u]  = __ldg(&reinterpret_cast<const float4*>(edge_attr)
                                  [(size_t)e * 16 + cc]);
                rr[u] = __ldg(&recv[e]);
            }
            #pragma unroll
            for (int u = 0; u < 4; u++) {
                red_add_v4(g_sums + (size_t)rr[u] * D + cc * 4, v[u]);
                if (cc == 0) atomicAdd(&g_cnt[rr[u]], 1.0f);
            }
        }
        return;
    }

    if (blockIdx.x < SC_BLOCKS + NB_NODE) {
        // ===== node projection: hpre[n][j] = node[n][0:64] . W1[0:64][j] =====
        const int tile = (blockIdx.x - SC_BLOCKS) * 64;
        const int lane = tid & 31, p = tid >> 5;
        for (int i = tid; i < D * LATENT; i += 256) sW[i] = W1[i];
        __syncthreads();

        const int n0 = tile + p * 8;
        float acc[8] = {};
        #pragma unroll 4
        for (int k4 = 0; k4 < 16; k4++) {
            float w0 = sW[(4 * k4 + 0) * LATENT + lane];
            float w1 = sW[(4 * k4 + 1) * LATENT + lane];
            float w2 = sW[(4 * k4 + 2) * LATENT + lane];
            float w3 = sW[(4 * k4 + 3) * LATENT + lane];
            #pragma unroll
            for (int i = 0; i < 8; i++) {
                int n = n0 + i;
                if (n < N_NODES) {
                    float4 x = __ldg(&reinterpret_cast<const float4*>(node_attr)
                                         [(size_t)n * 16 + k4]);
                    acc[i] = fmaf(x.x, w0, acc[i]);
                    acc[i] = fmaf(x.y, w1, acc[i]);
                    acc[i] = fmaf(x.z, w2, acc[i]);
                    acc[i] = fmaf(x.w, w3, acc[i]);
                }
            }
        }
        #pragma unroll
        for (int i = 0; i < 8; i++) {
            int n = n0 + i;
            if (n < N_NODES) g_hpre[(size_t)n * LATENT + lane] = acc[i];
        }
        return;
    }

    // ===== G[b][j] = b1[j] + global[b] . W1[128:192][j] =====
    {
        const int lane = tid & 31;
        for (int i = tid; i < D * LATENT; i += 256)
            sW[i] = W1[2 * D * LATENT + i];
        if (tid < LATENT) sb[tid] = b1[tid];
        __syncthreads();

        const int r0 = (tid >> 5) * 8;
        float acc[8];
        #pragma unroll
        for (int i = 0; i < 8; i++) acc[i] = sb[lane];
        #pragma unroll 4
        for (int k4 = 0; k4 < 16; k4++) {
            float w0 = sW[(4 * k4 + 0) * LATENT + lane];
            float w1 = sW[(4 * k4 + 1) * LATENT + lane];
            float w2 = sW[(4 * k4 + 2) * LATENT + lane];
            float w3 = sW[(4 * k4 + 3) * LATENT + lane];
            #pragma unroll
            for (int i = 0; i < 8; i++) {
                float4 x = __ldg(&reinterpret_cast<const float4*>(global_attr)
                                     [(size_t)(r0 + i) * 16 + k4]);
                acc[i] = fmaf(x.x, w0, acc[i]);
                acc[i] = fmaf(x.y, w1, acc[i]);
                acc[i] = fmaf(x.z, w2, acc[i]);
                acc[i] = fmaf(x.w, w3, acc[i]);
            }
        }
        #pragma unroll
        for (int i = 0; i < 8; i++) g_G[(r0 + i) * LATENT + lane] = acc[i];
    }
}

// ---------------------------------------------------------------------------
// Kernel B: mean staging + edge-half layer1 (FFMA2, LDS.128) + relu + layer2.
// Block = 64-node tile; warp owns 8 nodes. Stride-66 (16B-aligned rows).
// ---------------------------------------------------------------------------
__global__ __launch_bounds__(256)
void mlp_kernel(const float* __restrict__ W1,
                const float* __restrict__ W2,
                const float* __restrict__ b2,
                const int* __restrict__ ng,
                float* __restrict__ out) {
    __shared__ __align__(16) float2 sW1b[1024];            // 8 KB, W1 rows 64..127
    __shared__ float sW2[LATENT * OUT_DIM];                // 8 KB
    __shared__ float sb2[OUT_DIM];
    __shared__ __align__(16) float2 xs2[32 * XS2_STRIDE];  // 16.9 KB (reused for h)

    const int tid = threadIdx.x;
    const int tile = blockIdx.x * 64;
    const int lane = tid & 31, p = tid >> 5;
    const int nbase = tile + p * 8;

    for (int idx = tid; idx < 1024; idx += 256) {
        int k2 = idx >> 5, j = idx & 31;
        sW1b[idx] = make_float2(W1[(D + 2 * k2) * LATENT + j],
                                (float)W1[(D + 2 * k2 + 1) * LATENT + j]);
    }
    for (int i = tid; i < LATENT * OUT_DIM; i += 256) sW2[i] = W2[i];
    if (tid < OUT_DIM) sb2[tid] = b2[tid];

    // init accumulators: lo = hpre + G, hi = 0
    uint64_t a2[8];
    #pragma unroll
    for (int i = 0; i < 8; i++) {
        int n = nbase + i;
        float init = 0.f;
        if (n < N_NODES) {
            int g = __ldg(&ng[n]);
            init = g_hpre[(size_t)n * LATENT + lane] + g_G[g * LATENT + lane];
        }
        a2[i] = pack2(init, 0.f);
    }

    // stage mean aggregated edges, interleaved-k float2
    const int kq = tid & 15, srow = tid >> 4;
    #pragma unroll
    for (int it = 0; it < 4; it++) {
        int nn = it * 16 + srow, n = tile + nn;
        float4 v = make_float4(0.f, 0.f, 0.f, 0.f);
        if (n < N_NODES) {
            v = reinterpret_cast<const float4*>(g_sums)[(size_t)n * 16 + kq];
            float inv = 1.0f / fmaxf(g_cnt[n], 1.0f);
            v.x *= inv; v.y *= inv; v.z *= inv; v.w *= inv;
        }
        xs2[(2 * kq + 0) * XS2_STRIDE + nn] = make_float2(v.x, v.y);
        xs2[(2 * kq + 1) * XS2_STRIDE + nn] = make_float2(v.z, v.w);
    }
    __syncthreads();

    // re-zero this tile's scratch — FULL rows: 64 nodes x 16 float4
    {
        float4 z = make_float4(0.f, 0.f, 0.f, 0.f);
        #pragma unroll
        for (int s = 0; s < 4; s++) {
            int item = tid + 256 * s;             // 0..1023
            int n = tile + (item >> 4);
            if (n < N_NODES)
                reinterpret_cast<float4*>(g_sums)[(size_t)n * 16 + (item & 15)] = z;
        }
        if (tid < 64 && tile + tid < N_NODES) g_cnt[tile + tid] = 0.f;
    }

    // edge half of layer 1: FFMA2 over k-pairs, x via LDS.128
    #pragma unroll 4
    for (int k2 = 0; k2 < 32; k2++) {
        uint64_t w2 = *reinterpret_cast<const uint64_t*>(&sW1b[k2 * 32 + lane]);
        const ulonglong2* xr =
            reinterpret_cast<const ulonglong2*>(&xs2[k2 * XS2_STRIDE + p * 8]);
        ulonglong2 xa = xr[0], xb = xr[1], xc = xr[2], xd = xr[3];
        ffma2(a2[0], xa.x, w2); ffma2(a2[1], xa.y, w2);
        ffma2(a2[2], xb.x, w2); ffma2(a2[3], xb.y, w2);
        ffma2(a2[4], xc.x, w2); ffma2(a2[5], xc.y, w2);
        ffma2(a2[6], xd.x, w2); ffma2(a2[7], xd.y, w2);
    }
    __syncthreads();   // xs2 reads done; reuse as h buffer

    // relu, park h j-major (two STS.128)
    float* hs2 = reinterpret_cast<float*>(xs2);
    float h[8];
    #pragma unroll
    for (int i = 0; i < 8; i++) {
        float lo, hi; unpack2(a2[i], lo, hi);
        h[i] = fmaxf(lo + hi, 0.f);
    }
    {
        ulonglong2 t0, t1;
        t0.x = pack2(h[0], h[1]); t0.y = pack2(h[2], h[3]);
        t1.x = pack2(h[4], h[5]); t1.y = pack2(h[6], h[7]);
        ulonglong2* dst = reinterpret_cast<ulonglong2*>(
            &hs2[lane * (2 * XS2_STRIDE) + p * 8]);
        dst[0] = t0; dst[1] = t1;
    }
    __syncthreads();

    // layer 2: h via LDS.128
    uint64_t o2[4][2];
    #pragma unroll
    for (int q = 0; q < 4; q++) {
        o2[q][0] = pack2(sb2[lane], sb2[lane]);
        o2[q][1] = pack2(sb2[lane + 32], sb2[lane + 32]);
    }
    #pragma unroll 4
    for (int j = 0; j < LATENT; j++) {
        float wa = sW2[j * OUT_DIM + lane];
        float wb = sW2[j * OUT_DIM + lane + 32];
        uint64_t w0 = pack2(wa, wa);
        uint64_t w1 = pack2(wb, wb);
        const ulonglong2* hr = reinterpret_cast<const ulonglong2*>(
            &hs2[j * (2 * XS2_STRIDE) + p * 8]);
        ulonglong2 ha = hr[0], hb = hr[1];
        ffma2(o2[0][0], ha.x, w0); ffma2(o2[0][1], ha.x, w1);
        ffma2(o2[1][0], ha.y, w0); ffma2(o2[1][1], ha.y, w1);
        ffma2(o2[2][0], hb.x, w0); ffma2(o2[2][1], hb.x, w1);
        ffma2(o2[3][0], hb.y, w0); ffma2(o2[3][1], hb.y, w1);
    }

    #pragma unroll
    for (int q = 0; q < 4; q++) {
        int n0 = nbase + 2 * q;
        float a0, c0, a1, c1;
        unpack2(o2[q][0], a0, c0);
        unpack2(o2[q][1], a1, c1);
        if (n0 < N_NODES) {
            out[(size_t)n0 * OUT_DIM + lane]      = a0;
            out[(size_t)n0 * OUT_DIM + lane + 32] = a1;
        }
        if (n0 + 1 < N_NODES) {
            out[(size_t)(n0 + 1) * OUT_DIM + lane]      = c0;
            out[(size_t)(n0 + 1) * OUT_DIM + lane + 32] = c1;
        }
    }
}

// ---------------------------------------------------------------------------
// Kernel C: nop (makes L=3 so ncu -s 5 -c 1 captures the scatter kernel)
// ---------------------------------------------------------------------------
__global__ void nop_kernel() {}

// ---------------------------------------------------------------------------
extern "C" void kernel_launch(void* const* d_in, const int* in_sizes, int n_in,
                              void* d_out, int out_size) {
    const float* node_attr   = (const float*)d_in[0];
    const float* edge_attr   = (const float*)d_in[1];
    const float* global_attr = (const float*)d_in[2];
    const float* W1          = (const float*)d_in[3];
    const float* b1          = (const float*)d_in[4];
    const float* W2          = (const float*)d_in[5];
    const float* b2          = (const float*)d_in[6];
    const int*   recv        = (const int*)d_in[7];
    const int*   ng          = (const int*)d_in[8];
    float* out = (float*)d_out;

    // A) batched edge scatter + node projection + G
    scatter_kernel<<<SC_BLOCKS + NB_NODE + 1, 256>>>(edge_attr, recv, node_attr,
                                                     global_attr, W1, b1);

    // B) mean + edge-half layer1 + relu + layer2 (+ scratch re-zero)
    mlp_kernel<<<(N_NODES + 63) / 64, 256>>>(W1, W2, b2, ng, out);

    // C) nop — shifts ncu capture onto scatter_kernel
    nop_kernel<<<1, 32>>>();
}